// round 3
// baseline (speedup 1.0000x reference)
#include <cuda_runtime.h>
#include <math.h>

// Tree-GRU reduction: B=32, L=4096, D=256.
// Per level (n -> n/2): h0 = 0.5*(hL+hR); h1 = GRU(xL,h0); h2 = GRU(xR,h1);
// emb' = 0.5*(h1+h2); hs' = h2. 12 levels, output emb[:,0] (B,256) fp32.
//
// Each GRU cell = one fused GEMM: A=[x|h] (K=512) x Wcat[512,768] + epilogue.
// n-gate needs i_n and h_n separately -> snapshot accumulator at K=256.

#define DH 256
#define NGATE 768
#define KTOT 512
#define BM 128           // rows per CTA
#define DT 32            // output dims per CTA (16 f32x2 pairs)
#define KC 64            // K chunk
#define NTH 256
#define SAS 66           // padded sA row stride (floats): conflict-free broadcast reads
#define SMEM_FLOATS (BM*SAS + KC*96)
#define SMEM_BYTES (SMEM_FLOATS*4)

#define MAXELEM (32*2048*256)

__device__ float g_Wcat[KTOT*NGATE];     // [k][g], k<256: W_ih^T, k>=256: W_hh^T
__device__ float g_h1buf[MAXELEM];
__device__ float g_embA[MAXELEM];
__device__ float g_embB[MAXELEM];
__device__ float g_hsA[MAXELEM];
__device__ float g_hsB[MAXELEM];

__global__ void build_wcat(const float* __restrict__ wih, const float* __restrict__ whh) {
    int idx = blockIdx.x*blockDim.x + threadIdx.x;
    if (idx >= KTOT*NGATE) return;
    int k = idx / NGATE, g = idx - k*NGATE;
    g_Wcat[idx] = (k < DH) ? wih[g*DH + k] : whh[g*DH + (k - DH)];
}

__device__ __forceinline__ unsigned long long splat2(float a) {
    unsigned long long r;
    asm("mov.b64 %0, {%1, %1};" : "=l"(r) : "f"(a));
    return r;
}
__device__ __forceinline__ void fma2(unsigned long long& acc, unsigned long long a,
                                     unsigned long long b) {
    asm("fma.rn.f32x2 %0, %1, %2, %0;" : "+l"(acc) : "l"(a), "l"(b));
}
__device__ __forceinline__ float2 unpk(unsigned long long v) {
    float2 r;
    asm("mov.b64 {%0, %1}, %2;" : "=f"(r.x), "=f"(r.y) : "l"(v));
    return r;
}

__device__ __forceinline__ float sigmoid_acc(float x) {
    return 1.f / (1.f + expf(-x));
}
// exp-based tanh: stays ~1e-6 accurate even if expf -> __expf under fast math
// (avoids MUFU.TANH ~2^-11 error accumulating over 24 sequential cells).
__device__ __forceinline__ float tanh_acc(float x) {
    float ax = fabsf(x);
    float t = expf(-2.f * ax);
    float r = (1.f - t) / (1.f + t);
    return (x < 0.f) ? -r : r;
}

// A element gather for rows m, k range [k0,k0+4). Chunks never straddle k=256.
template<int MODE>
__device__ __forceinline__ float4 loadA4(const float* __restrict__ X,
                                         const float* __restrict__ H,
                                         int m, int k0, int n, int lgP, int M) {
    if (m >= M) return make_float4(0.f, 0.f, 0.f, 0.f);
    int b = m >> lgP;
    int j = m & ((1 << lgP) - 1);
    if (k0 < DH) {
        // x part: mode0 -> xL (2j), mode1 -> xR (2j+1)
        size_t base = ((size_t)b * n + 2*j + MODE) * DH;
        return *(const float4*)(X + base + k0);
    } else {
        int kh = k0 - DH;
        if (MODE == 0) {
            if (H == nullptr) return make_float4(0.f, 0.f, 0.f, 0.f);  // level 0: hs=0
            size_t bl = ((size_t)b * n + 2*j) * DH;
            float4 a = *(const float4*)(H + bl + kh);
            float4 c = *(const float4*)(H + bl + DH + kh);
            return make_float4(0.5f*(a.x+c.x), 0.5f*(a.y+c.y),
                               0.5f*(a.z+c.z), 0.5f*(a.w+c.w));
        } else {
            return *(const float4*)(H + (size_t)m * DH + kh);  // h1 dense [M][256]
        }
    }
}

// MODE 0: X=embeds, H=hs(level in, may be null), out1=h1 dense.
// MODE 1: X=embeds, H=h1 dense,  out1=hs_next [B][P][256], out2=emb_next.
template<int MODE>
__global__ __launch_bounds__(NTH, 2) void cell_kernel(
    const float* __restrict__ X, const float* __restrict__ H,
    const float* __restrict__ bih, const float* __restrict__ bhh,
    float* __restrict__ out1, float* __restrict__ out2,
    int n, int lgP, int M)
{
    extern __shared__ float smem[];
    float* sA = smem;             // [BM][SAS]  A tile (k-major per row)
    float* sW = smem + BM*SAS;    // [KC][3][32] weight tile (r,z,n blocks)

    const int t = threadIdx.x;
    const int rowBase = blockIdx.x * BM;
    const int d0 = blockIdx.y * DT;
    const int dp = t & 15;        // dim pair 0..15  -> dims d0+2dp, d0+2dp+1
    const int rg = t >> 4;        // row group 0..15 -> rows rg*8 .. rg*8+7
    const int r0 = rg * 8;

    unsigned long long acc[8][3];
    unsigned long long sn[8];
    #pragma unroll
    for (int i = 0; i < 8; ++i) {
        acc[i][0] = 0ull; acc[i][1] = 0ull; acc[i][2] = 0ull; sn[i] = 0ull;
    }

    const int lrow = t >> 4;      // staging: 16 rows per pass
    const int kq = t & 15;        // staging: float4 index within chunk

    for (int c8 = 0; c8 < 8; ++c8) {
        const int kbase = c8 * KC;
        __syncthreads();
        // ---- stage A chunk [BM][KC] (global-coalesced float4, row-major smem) ----
        #pragma unroll
        for (int p = 0; p < 8; ++p) {
            int row = p*16 + lrow;
            int k0 = kbase + kq*4;
            float4 v = loadA4<MODE>(X, H, rowBase + row, k0, n, lgP, M);
            float* dst = &sA[row*SAS + kq*4];
            *(float2*)dst = make_float2(v.x, v.y);
            *(float2*)(dst+2) = make_float2(v.z, v.w);
        }
        // ---- stage W chunk [KC][3][32] ----
        {
            int c = t & 31;
            int ksub = t >> 5;   // 0..7
            #pragma unroll
            for (int blk = 0; blk < 3; ++blk)
                #pragma unroll
                for (int s = 0; s < 8; ++s) {
                    int kk = s*8 + ksub;
                    sW[kk*96 + blk*32 + c] =
                        g_Wcat[(size_t)(kbase + kk)*NGATE + blk*DH + d0 + c];
                }
        }
        __syncthreads();
        // ---- FFMA2 mainloop: 8 rows x 3 gates x 2 dims per thread per k ----
        #pragma unroll 16
        for (int kk = 0; kk < KC; ++kk) {
            unsigned long long wr = *(const unsigned long long*)&sW[kk*96      + 2*dp];
            unsigned long long wz = *(const unsigned long long*)&sW[kk*96 + 32 + 2*dp];
            unsigned long long wn = *(const unsigned long long*)&sW[kk*96 + 64 + 2*dp];
            #pragma unroll
            for (int i = 0; i < 8; ++i) {
                unsigned long long a2 = splat2(sA[(r0+i)*SAS + kk]);
                fma2(acc[i][0], a2, wr);
                fma2(acc[i][1], a2, wz);
                fma2(acc[i][2], a2, wn);
            }
        }
        if (c8 == 3) {   // phase boundary k=256: snapshot i_n
            #pragma unroll
            for (int i = 0; i < 8; ++i) sn[i] = acc[i][2];
        }
    }

    // ---- epilogue: gates -> GRU cell -> outputs ----
    const int d = d0 + 2*dp;
    float2 Br  = make_float2(bih[d]      + bhh[d],      bih[d+1]      + bhh[d+1]);
    float2 Bz  = make_float2(bih[DH+d]   + bhh[DH+d],   bih[DH+d+1]   + bhh[DH+d+1]);
    float2 Bin = make_float2(bih[2*DH+d],               bih[2*DH+d+1]);
    float2 Bhn = make_float2(bhh[2*DH+d],               bhh[2*DH+d+1]);

    #pragma unroll
    for (int i = 0; i < 8; ++i) {
        int m = rowBase + r0 + i;
        if (m >= M) break;
        int b = m >> lgP;
        int j = m & ((1 << lgP) - 1);
        float2 ar = unpk(acc[i][0]);
        float2 az = unpk(acc[i][1]);
        float2 an = unpk(acc[i][2]);
        float2 si = unpk(sn[i]);

        float2 hp;
        if (MODE == 0) {
            if (H) {
                size_t bl = ((size_t)b * n + 2*j) * DH;
                float2 a = *(const float2*)(H + bl + d);
                float2 c = *(const float2*)(H + bl + DH + d);
                hp = make_float2(0.5f*(a.x+c.x), 0.5f*(a.y+c.y));
            } else hp = make_float2(0.f, 0.f);
        } else {
            hp = *(const float2*)(H + (size_t)m * DH + d);   // = h1
        }

        float2 ho;
        {
            float r  = sigmoid_acc(ar.x + Br.x);
            float z  = sigmoid_acc(az.x + Bz.x);
            float iv = si.x + Bin.x;
            float hn = (an.x - si.x) + Bhn.x;
            float nv = tanh_acc(iv + r*hn);
            ho.x = (1.f - z)*nv + z*hp.x;
        }
        {
            float r  = sigmoid_acc(ar.y + Br.y);
            float z  = sigmoid_acc(az.y + Bz.y);
            float iv = si.y + Bin.y;
            float hn = (an.y - si.y) + Bhn.y;
            float nv = tanh_acc(iv + r*hn);
            ho.y = (1.f - z)*nv + z*hp.y;
        }

        if (MODE == 0) {
            *(float2*)(out1 + (size_t)m * DH + d) = ho;               // h1
        } else {
            size_t oi = (((size_t)b << lgP) + j) * DH + d;            // [B][P][256]
            *(float2*)(out1 + oi) = ho;                               // hs' = h2
            float2 e = make_float2(0.5f*(hp.x + ho.x), 0.5f*(hp.y + ho.y));
            *(float2*)(out2 + oi) = e;                                // emb' = 0.5(h1+h2)
        }
    }
}

extern "C" void kernel_launch(void* const* d_in, const int* in_sizes, int n_in,
                              void* d_out, int out_size) {
    (void)in_sizes; (void)n_in; (void)out_size;
    const float* leaf = (const float*)d_in[0];
    const float* Wih  = (const float*)d_in[1];
    const float* Whh  = (const float*)d_in[2];
    const float* bih  = (const float*)d_in[3];
    const float* bhh  = (const float*)d_in[4];
    float* out = (float*)d_out;

    float *h1, *eA, *eB, *hA, *hB;
    cudaGetSymbolAddress((void**)&h1, g_h1buf);
    cudaGetSymbolAddress((void**)&eA, g_embA);
    cudaGetSymbolAddress((void**)&eB, g_embB);
    cudaGetSymbolAddress((void**)&hA, g_hsA);
    cudaGetSymbolAddress((void**)&hB, g_hsB);

    cudaFuncSetAttribute((const void*)cell_kernel<0>,
                         cudaFuncAttributeMaxDynamicSharedMemorySize, SMEM_BYTES);
    cudaFuncSetAttribute((const void*)cell_kernel<1>,
                         cudaFuncAttributeMaxDynamicSharedMemorySize, SMEM_BYTES);

    build_wcat<<<(KTOT*NGATE + NTH - 1)/NTH, NTH>>>(Wih, Whh);

    const float* embIn = leaf;
    const float* hsIn  = nullptr;
    int cur = 0;
    for (int lvl = 0; lvl < 12; ++lvl) {
        int nn  = 4096 >> lvl;
        int lgP = 11 - lvl;          // P = nn/2 = 1<<lgP
        int M   = 32 << lgP;         // B * P
        float* embOut = (lvl == 11) ? out : (cur ? eB : eA);
        float* hsOut  = cur ? hB : hA;
        dim3 grid((M + BM - 1)/BM, DH/DT);
        cell_kernel<0><<<grid, NTH, SMEM_BYTES>>>(embIn, hsIn, bih, bhh,
                                                  h1, nullptr, nn, lgP, M);
        cell_kernel<1><<<grid, NTH, SMEM_BYTES>>>(embIn, h1, bih, bhh,
                                                  hsOut, embOut, nn, lgP, M);
        embIn = embOut;
        hsIn  = hsOut;
        cur ^= 1;
    }
}

// round 6
// speedup vs baseline: 2.0135x; 2.0135x over previous
#include <cuda_runtime.h>
#include <cuda_bf16.h>
#include <cstdint>
#include <math.h>

// ============================================================================
// Tree-GRU via mma.sync (HMMA) bf16 3-term split GEMMs.  B=32, L=4096, D=256.
// Per level: prep (A split) -> cell1 GEMM -> cell2 GEMM.
// A = [x | h] (K=512) bf16 hi/lo;  W = [k][gate*256+d] bf16 hi/lo.
// Gate blocks per CTA (N): r(K512), z(K512), i_n(K<256), h_n(K>=256).
// ============================================================================

#define DH 256
#define MROWS_MAX 65536
#define ASTRIDE ((size_t)MROWS_MAX * 512)          // elems per term
#define ABYTES  (ASTRIDE * 2)                      // bytes per term
#define WSTRIDE ((size_t)4 * 192 * 512)
#define WBYTES  (WSTRIDE * 2)
#define EMB_ELEMS (32 * 2048 * 256)

__device__ __nv_bfloat16 g_A1[2 * ASTRIDE];   // [term][m][512]
__device__ __nv_bfloat16 g_A2[2 * ASTRIDE];
__device__ __nv_bfloat16 g_Wb[2 * WSTRIDE];   // [term][dblk][192][512]
__device__ float g_h1[MROWS_MAX * DH];
__device__ float g_embA[EMB_ELEMS];
__device__ float g_embB[EMB_ELEMS];
__device__ float g_hsA[EMB_ELEMS];
__device__ float g_hsB[EMB_ELEMS];

// ---------------- PTX helpers ----------------
__device__ __forceinline__ uint32_t smem_u32(const void* p) {
    uint32_t a;
    asm("{ .reg .u64 t; cvta.to.shared.u64 t, %1; cvt.u32.u64 %0, t; }"
        : "=r"(a) : "l"(p));
    return a;
}
__device__ __forceinline__ void cpasync16(uint32_t dst, const void* src) {
    asm volatile("cp.async.cg.shared.global [%0], [%1], 16;"
                 :: "r"(dst), "l"(src) : "memory");
}
__device__ __forceinline__ void cpcommit() {
    asm volatile("cp.async.commit_group;" ::: "memory");
}
template<int N>
__device__ __forceinline__ void cpwait() {
    asm volatile("cp.async.wait_group %0;" :: "n"(N) : "memory");
}
__device__ __forceinline__ void ldsm4(uint32_t r[4], uint32_t addr) {
    asm volatile("ldmatrix.sync.aligned.m8n8.x4.shared.b16 {%0,%1,%2,%3}, [%4];"
                 : "=r"(r[0]), "=r"(r[1]), "=r"(r[2]), "=r"(r[3]) : "r"(addr));
}
__device__ __forceinline__ void mma16816(float c[4], const uint32_t a[4],
                                         uint32_t b0, uint32_t b1) {
    asm volatile("mma.sync.aligned.m16n8k16.row.col.f32.bf16.bf16.f32 "
                 "{%0,%1,%2,%3}, {%4,%5,%6,%7}, {%8,%9}, {%0,%1,%2,%3};"
                 : "+f"(c[0]), "+f"(c[1]), "+f"(c[2]), "+f"(c[3])
                 : "r"(a[0]), "r"(a[1]), "r"(a[2]), "r"(a[3]),
                   "r"(b0), "r"(b1));
}
#define SW128(x) ((x) ^ (((x) >> 3) & 0x70))

// ---------------- math helpers ----------------
__device__ __forceinline__ float sigacc(float x) { return 1.f / (1.f + expf(-x)); }
__device__ __forceinline__ float tanhacc(float x) {
    float ax = fabsf(x);
    float t = expf(-2.f * ax);
    float r = (1.f - t) / (1.f + t);
    return (x < 0.f) ? -r : r;
}
__device__ __forceinline__ uint32_t pk2(float a, float b) {
    __nv_bfloat162 h = __floats2bfloat162_rn(a, b);
    return *(uint32_t*)&h;
}
__device__ __forceinline__ float2 ub2(uint32_t u) {
    __nv_bfloat162 h = *(__nv_bfloat162*)&u;
    return make_float2(__bfloat162float(h.x), __bfloat162float(h.y));
}
__device__ __forceinline__ void split1(float v, float& hi, float& lo) {
    __nv_bfloat16 h = __float2bfloat16(v);
    hi = __bfloat162float(h);
    lo = v - hi;
}
__device__ __forceinline__ void split4(float4 v, uint2& hi, uint2& lo) {
    float hx, lx, hy, ly, hz, lz, hw, lw;
    split1(v.x, hx, lx); split1(v.y, hy, ly);
    split1(v.z, hz, lz); split1(v.w, hw, lw);
    hi = make_uint2(pk2(hx, hy), pk2(hz, hw));
    lo = make_uint2(pk2(lx, ly), pk2(lz, lw));
}

// ---------------- weight prep: g_Wb[term][dblk][gate*64+dd][k] ----------------
__global__ void wprep(const float* __restrict__ wih, const float* __restrict__ whh) {
    int idx = blockIdx.x * blockDim.x + threadIdx.x;   // over 4*192*512
    if (idx >= 4 * 192 * 512) return;
    int k = idx & 511;
    int rowall = idx >> 9;         // blk*192 + gate*64 + dd
    int blk = rowall / 192;
    int rr = rowall - blk * 192;
    int gate = rr >> 6;
    int dd = rr & 63;
    int g = gate * 256 + blk * 64 + dd;
    float v = (k < 256) ? wih[g * 256 + k] : whh[g * 256 + (k - 256)];
    float hi, lo; split1(v, hi, lo);
    g_Wb[idx] = __float2bfloat16(hi);
    g_Wb[WSTRIDE + idx] = __float2bfloat16(lo);
}

// ---------------- A prep: fill A1 (x=xL, h=h0) and A2 x-part (xR) ------------
template<int FIRST>
__global__ void prep_kernel(const float* __restrict__ emb, const float* __restrict__ hs,
                            int n, int lgP, int M) {
    int idx = blockIdx.x * blockDim.x + threadIdx.x;   // M*128 threads
    if (idx >= M * 128) return;
    int m = idx >> 7;
    int kq = idx & 127;
    int b = m >> lgP;
    int j = m & ((1 << lgP) - 1);
    size_t rowL = ((size_t)(b * n + 2 * j)) * 256;
    char* A1 = (char*)g_A1;
    char* A2 = (char*)g_A2;
    if (kq < 64) {
        int k = kq * 4;
        float4 xl = *(const float4*)(emb + rowL + k);
        float4 xr = *(const float4*)(emb + rowL + 256 + k);
        uint2 hi, lo;
        size_t off = (size_t)m * 1024 + (size_t)k * 2;
        split4(xl, hi, lo);
        *(uint2*)(A1 + off) = hi;
        *(uint2*)(A1 + ABYTES + off) = lo;
        split4(xr, hi, lo);
        *(uint2*)(A2 + off) = hi;
        *(uint2*)(A2 + ABYTES + off) = lo;
    } else {
        int k = (kq - 64) * 4;
        float4 h0;
        if (FIRST) {
            h0 = make_float4(0.f, 0.f, 0.f, 0.f);
        } else {
            float4 a = *(const float4*)(hs + rowL + k);
            float4 c = *(const float4*)(hs + rowL + 256 + k);
            h0 = make_float4(0.5f * (a.x + c.x), 0.5f * (a.y + c.y),
                             0.5f * (a.z + c.z), 0.5f * (a.w + c.w));
        }
        uint2 hi, lo;
        split4(h0, hi, lo);
        size_t off = (size_t)m * 1024 + 512 + (size_t)k * 2;
        *(uint2*)(A1 + off) = hi;
        *(uint2*)(A1 + ABYTES + off) = lo;
    }
}

// ---------------- GEMM cell kernel (mma.sync) ----------------
// Dynamic smem: 2 buffers x 81920B (Ahi 16K | Alo 16K | Whi 24K | Wlo 24K),
// epilogue overlays 4 planes of [128][68] fp32 (34816B each), bias at 163840.
#define SM_BUF 81920
#define PLANE_B 34816
#define PLANE_F 8704
#define SM_TOTAL (2 * SM_BUF + 2048)

template<int MODE>
__device__ __forceinline__ void stage_chunk(
    uint32_t sbt, int buf, const char* Ab, int rowBase, int dblk, int c) {
    const char* Wsrc = (const char*)g_Wb;
    uint32_t bb = sbt + buf * SM_BUF;
    int t = threadIdx.x;
    #pragma unroll
    for (int p = 0; p < 4; ++p) {                      // A: 2 terms x 128 x 128B
        int u = t + 512 * p;
        int term = u >> 10;
        int rem = u & 1023;
        int row = rem >> 3, seg = rem & 7;
        const char* src = Ab + (size_t)term * ABYTES +
                          (size_t)(rowBase + row) * 1024 + (size_t)c * 128 + seg * 16;
        cpasync16(bb + term * 16384 + SW128(row * 128 + seg * 16), src);
    }
    #pragma unroll
    for (int p = 0; p < 6; ++p) {                      // W: 2 terms x 192 x 128B
        int u = t + 512 * p;
        int term = (u >= 1536) ? 1 : 0;
        int rem = u - term * 1536;
        int row = rem >> 3, seg = rem & 7;
        const char* src = Wsrc + (size_t)term * WBYTES +
                          (size_t)(dblk * 192 + row) * 1024 + (size_t)c * 128 + seg * 16;
        cpasync16(bb + 32768 + term * 24576 + SW128(row * 128 + seg * 16), src);
    }
}

template<int MODE>
__global__ __launch_bounds__(512, 1) void gemm_cell(
    const __nv_bfloat16* __restrict__ Abase,
    const float* __restrict__ bih, const float* __restrict__ bhh,
    float* __restrict__ h1buf,                 // MODE0: write, MODE1: read
    __nv_bfloat16* __restrict__ A2w,           // MODE0: write h-part
    float* __restrict__ hsOut, float* __restrict__ embOut,  // MODE1
    int M)
{
    extern __shared__ char smem[];
    const uint32_t sbt = smem_u32(smem);
    const int t = threadIdx.x;
    const int lane = t & 31, wid = t >> 5;
    const int mi = wid & 3, nb = wid >> 2;     // nb: 0=r 1=z 2=i_n 3=h_n
    const int rowBase = blockIdx.x * 128;
    const int dblk = blockIdx.y;
    const int d0g = dblk * 64;
    const char* Ab = (const char*)Abase;

    // stage biases (combined) into smem tail
    float* bs = (float*)(smem + 163840);
    if (t < 64) {
        int dg = d0g + t;
        bs[t]       = bih[dg] + bhh[dg];
        bs[64 + t]  = bih[256 + dg] + bhh[256 + dg];
        bs[128 + t] = bih[512 + dg];
        bs[192 + t] = bhh[512 + dg];
    }

    // per-lane ldmatrix row precompute
    const int rsel = lane & 15, half = lane >> 4;
    const int m0 = mi * 32;
    const int wrow = (nb >= 2) ? 128 : nb * 64;
    int rA0 = m0 + rsel,      aoff0 = rA0 * 128, ax0 = rA0 & 7;
    int rA1 = m0 + 16 + rsel, aoff1 = rA1 * 128, ax1 = rA1 & 7;
    int boff[4], bx[4];
    #pragma unroll
    for (int n16 = 0; n16 < 4; ++n16) {
        int rB = wrow + n16 * 16 + rsel;
        boff[n16] = rB * 128;
        bx[n16] = rB & 7;
    }

    float acc[2][8][4];
    #pragma unroll
    for (int a = 0; a < 2; ++a)
        #pragma unroll
        for (int b = 0; b < 8; ++b)
            #pragma unroll
            for (int e = 0; e < 4; ++e) acc[a][b][e] = 0.f;

    stage_chunk<MODE>(sbt, 0, Ab, rowBase, dblk, 0); cpcommit();
    stage_chunk<MODE>(sbt, 1, Ab, rowBase, dblk, 1); cpcommit();

    for (int c = 0; c < 8; ++c) {
        if (c < 7) cpwait<1>(); else cpwait<0>();
        __syncthreads();
        bool act = (nb < 2) || (nb == 2 && c < 4) || (nb == 3 && c >= 4);
        if (act) {
            uint32_t bb = sbt + (c & 1) * SM_BUF;
            uint32_t bA = bb, bAl = bb + 16384, bW = bb + 32768, bWl = bb + 57344;
            #pragma unroll
            for (int kb = 0; kb < 4; ++kb) {
                int ch = 2 * kb + half;
                uint32_t ah[2][4], al[2][4];
                ldsm4(ah[0], bA  + aoff0 + ((ch ^ ax0) << 4));
                ldsm4(ah[1], bA  + aoff1 + ((ch ^ ax1) << 4));
                ldsm4(al[0], bAl + aoff0 + ((ch ^ ax0) << 4));
                ldsm4(al[1], bAl + aoff1 + ((ch ^ ax1) << 4));
                #pragma unroll
                for (int n16 = 0; n16 < 4; ++n16) {
                    uint32_t bh[4], bl[4];
                    uint32_t wo = boff[n16] + ((ch ^ bx[n16]) << 4);
                    ldsm4(bh, bW + wo);
                    ldsm4(bl, bWl + wo);
                    #pragma unroll
                    for (int tm = 0; tm < 2; ++tm) {
                        mma16816(acc[tm][2*n16],   ah[tm], bh[0], bh[2]);
                        mma16816(acc[tm][2*n16+1], ah[tm], bh[1], bh[3]);
                        mma16816(acc[tm][2*n16],   ah[tm], bl[0], bl[2]);
                        mma16816(acc[tm][2*n16+1], ah[tm], bl[1], bl[3]);
                        mma16816(acc[tm][2*n16],   al[tm], bh[0], bh[2]);
                        mma16816(acc[tm][2*n16+1], al[tm], bh[1], bh[3]);
                    }
                }
            }
        }
        __syncthreads();
        if (c + 2 < 8) { stage_chunk<MODE>(sbt, c & 1, Ab, rowBase, dblk, c + 2); cpcommit(); }
    }

    // ---- store accumulators to smem planes [nb][128][68] ----
    {
        float* plane = (float*)(smem + nb * PLANE_B);
        int r0 = lane >> 2, c0 = (lane & 3) * 2;
        #pragma unroll
        for (int tm = 0; tm < 2; ++tm)
            #pragma unroll
            for (int tn = 0; tn < 8; ++tn) {
                int mrow = m0 + tm * 16 + r0;
                int ncol = tn * 8 + c0;
                *(float2*)(plane + mrow * 68 + ncol) =
                    make_float2(acc[tm][tn][0], acc[tm][tn][1]);
                *(float2*)(plane + (mrow + 8) * 68 + ncol) =
                    make_float2(acc[tm][tn][2], acc[tm][tn][3]);
            }
    }
    __syncthreads();

    // ---- fused GRU epilogue: thread -> (row m = t>>2, 16 dims) ----
    const int m = t >> 2;
    const int dl0 = (t & 3) * 16;
    const int mg = rowBase + m;
    if (mg < M) {
        const float* pf = (const float*)smem;
        #pragma unroll
        for (int q4 = 0; q4 < 4; ++q4) {
            int dl = dl0 + q4 * 4;
            const float* p0 = pf + m * 68 + dl;
            float4 vr  = *(const float4*)(p0);
            float4 vz  = *(const float4*)(p0 + PLANE_F);
            float4 vni = *(const float4*)(p0 + 2 * PLANE_F);
            float4 vnh = *(const float4*)(p0 + 3 * PLANE_F);
            float ar[4] = {vr.x, vr.y, vr.z, vr.w};
            float az[4] = {vz.x, vz.y, vz.z, vz.w};
            float ai[4] = {vni.x, vni.y, vni.z, vni.w};
            float ahh[4] = {vnh.x, vnh.y, vnh.z, vnh.w};

            float hp[4];
            if (MODE == 0) {
                const char* hb = Ab + (size_t)mg * 1024 + 512 + (size_t)(d0g + dl) * 2;
                uint2 vhi = *(const uint2*)hb;
                uint2 vlo = *(const uint2*)(hb + ABYTES);
                float2 a0 = ub2(vhi.x), b0 = ub2(vlo.x);
                float2 a1 = ub2(vhi.y), b1 = ub2(vlo.y);
                hp[0] = a0.x + b0.x; hp[1] = a0.y + b0.y;
                hp[2] = a1.x + b1.x; hp[3] = a1.y + b1.y;
            } else {
                float4 h4 = *(const float4*)(h1buf + (size_t)mg * 256 + d0g + dl);
                hp[0] = h4.x; hp[1] = h4.y; hp[2] = h4.z; hp[3] = h4.w;
            }

            float ho[4];
            #pragma unroll
            for (int e = 0; e < 4; ++e) {
                int dloc = dl + e;
                float r = sigacc(ar[e] + bs[dloc]);
                float z = sigacc(az[e] + bs[64 + dloc]);
                float nv = tanhacc(ai[e] + bs[128 + dloc] + r * (ahh[e] + bs[192 + dloc]));
                ho[e] = (1.f - z) * nv + z * hp[e];
            }

            if (MODE == 0) {
                *(float4*)(h1buf + (size_t)mg * 256 + d0g + dl) =
                    make_float4(ho[0], ho[1], ho[2], ho[3]);
                float h0v, l0v, h1v, l1v, h2v, l2v, h3v, l3v;
                split1(ho[0], h0v, l0v); split1(ho[1], h1v, l1v);
                split1(ho[2], h2v, l2v); split1(ho[3], h3v, l3v);
                char* a2 = (char*)A2w + (size_t)mg * 1024 + 512 + (size_t)(d0g + dl) * 2;
                *(uint2*)a2 = make_uint2(pk2(h0v, h1v), pk2(h2v, h3v));
                *(uint2*)(a2 + ABYTES) = make_uint2(pk2(l0v, l1v), pk2(l2v, l3v));
            } else {
                *(float4*)(hsOut + (size_t)mg * 256 + d0g + dl) =
                    make_float4(ho[0], ho[1], ho[2], ho[3]);
                *(float4*)(embOut + (size_t)mg * 256 + d0g + dl) =
                    make_float4(0.5f * (hp[0] + ho[0]), 0.5f * (hp[1] + ho[1]),
                                0.5f * (hp[2] + ho[2]), 0.5f * (hp[3] + ho[3]));
            }
        }
    }
}

// ---------------- driver ----------------
extern "C" void kernel_launch(void* const* d_in, const int* in_sizes, int n_in,
                              void* d_out, int out_size) {
    (void)in_sizes; (void)n_in; (void)out_size;
    const float* leaf = (const float*)d_in[0];
    const float* Wih  = (const float*)d_in[1];
    const float* Whh  = (const float*)d_in[2];
    const float* bih  = (const float*)d_in[3];
    const float* bhh  = (const float*)d_in[4];
    float* out = (float*)d_out;

    __nv_bfloat16 *A1, *A2;
    float *h1, *eA, *eB, *hA, *hB;
    cudaGetSymbolAddress((void**)&A1, g_A1);
    cudaGetSymbolAddress((void**)&A2, g_A2);
    cudaGetSymbolAddress((void**)&h1, g_h1);
    cudaGetSymbolAddress((void**)&eA, g_embA);
    cudaGetSymbolAddress((void**)&eB, g_embB);
    cudaGetSymbolAddress((void**)&hA, g_hsA);
    cudaGetSymbolAddress((void**)&hB, g_hsB);

    cudaFuncSetAttribute(gemm_cell<0>, cudaFuncAttributeMaxDynamicSharedMemorySize, SM_TOTAL);
    cudaFuncSetAttribute(gemm_cell<1>, cudaFuncAttributeMaxDynamicSharedMemorySize, SM_TOTAL);

    wprep<<<(4 * 192 * 512 + 255) / 256, 256>>>(Wih, Whh);

    const float* embIn = leaf;
    const float* hsIn = nullptr;
    int cur = 0;
    for (int lvl = 0; lvl < 12; ++lvl) {
        int n = 4096 >> lvl;
        int lgP = 11 - lvl;
        int M = 32 << lgP;
        int pthreads = M * 128;
        if (lvl == 0)
            prep_kernel<1><<<pthreads / 256, 256>>>(embIn, nullptr, n, lgP, M);
        else
            prep_kernel<0><<<pthreads / 256, 256>>>(embIn, hsIn, n, lgP, M);

        dim3 grid((M + 127) / 128, 4);
        gemm_cell<0><<<grid, 512, SM_TOTAL>>>(A1, bih, bhh, h1, A2,
                                              nullptr, nullptr, M);
        float* embOut = (lvl == 11) ? out : (cur ? eB : eA);
        float* hsOut  = cur ? hB : hA;
        gemm_cell<1><<<grid, 512, SM_TOTAL>>>(A2, bih, bhh, h1, nullptr,
                                              hsOut, embOut, M);
        embIn = embOut;
        hsIn = hsOut;
        cur ^= 1;
    }
}